// round 7
// baseline (speedup 1.0000x reference)
#include <cuda_runtime.h>

#define NTHREADS 256
#define BLOCKS_PER_SM 3
#define NBLOCKS  (148 * BLOCKS_PER_SM)   // persistent grid for gather

// Duplicated row-pair layout: entry(y,x) = 4 float4 =
//   [tex(y,x).h0, tex(y,x).h1, tex(y+1,x).h0, tex(y+1,x).h1]   (y+1 clamped to 511)
// One bilinear sample = one contiguous 128B region (entries x0, x0+1).
#define DUP_F4 (512 * 512 * 4)           // float4 count per plane (2^20)
__device__ float4 g_dup[3][DUP_F4];      // 3 x 16.8MB = 50MB static scratch

__global__ void __launch_bounds__(256)
repack_kernel(const float4* __restrict__ p0,
              const float4* __restrict__ p1,
              const float4* __restrict__ p2)
{
    const int idx = blockIdx.x * 256 + threadIdx.x;   // one thread per output float4
    if (idx >= 3 * DUP_F4) return;
    const int q    = idx >> 20;            // plane
    const int r    = idx & (DUP_F4 - 1);
    const int ent  = r >> 2;               // entry = y*512 + x
    const int slot = r & 3;
    const int y    = ent >> 9;
    const int x    = ent & 511;
    const int yy   = (slot < 2) ? y : min(y + 1, 511);
    const int h    = slot & 1;
    const float4* src = (q == 0) ? p0 : (q == 1) ? p1 : p2;
    g_dup[q][r] = src[(((yy << 9) + x) << 1) + h];
}

struct PS { int base; float w0, w1; };   // w0/w1 = row-weight x (col0/col1 weight)

// Per-plane params for one lane (sub-lane s, row r = s>>1).
__device__ __forceinline__ PS plane_setup(float u, float v, int s, int r)
{
    // x = ((u+1)*512 - 1)*0.5 == u*256 + 255.5 (<=1 ulp; bilinear continuous)
    float x = fmaf(u, 256.0f, 255.5f);
    float y = fmaf(v, 256.0f, 255.5f);
    x = fminf(fmaxf(x, 0.0f), 511.0f);
    y = fminf(fmaxf(y, 0.0f), 511.0f);

    float xbf = fminf(floorf(x), 510.0f);
    float ybf = fminf(floorf(y), 510.0f);

    // a1 = weight of col xb+1 (== wx normally; ==1 exactly at border x=511)
    float a1 = x - xbf;
    float b1 = y - ybf;
    float rw = r ? b1 : (1.0f - b1);

    PS ps;
    ps.w0 = rw * (1.0f - a1);
    ps.w1 = rw * a1;
    ps.base = ((((int)ybf << 9) + (int)xbf) << 2);  // f4 idx of entry (yb, xb)
    return ps;
}

__global__ void __launch_bounds__(NTHREADS, BLOCKS_PER_SM)
geo_encoder_kernel(
    const float*  __restrict__ coords,   // [N,3]
    const float*  __restrict__ Wp,       // [8,24]
    const float*  __restrict__ bp,       // [8]
    float*        __restrict__ out,      // [N,8]
    int n)
{
    const float4* __restrict__ dxy = g_dup[0];
    const float4* __restrict__ dxz = g_dup[1];
    const float4* __restrict__ dyz = g_dup[2];

    const int t   = threadIdx.x;
    const int s   = t & 3;       // sub-lane in quad
    const int h   = s & 1;       // rank half (float4 slot within texel)
    const int r   = s >> 1;      // row (top/bottom) this lane loads; also output group
    const int grp = r;

    // W slice in registers: Wreg[j*12 + q*4 + rr] = W[4*grp+j][q*8 + h*4 + rr]
    float Wreg[48];
    float bias[4];
    const int row0 = 4 * grp;
    #pragma unroll
    for (int j = 0; j < 4; j++) {
        bias[j] = __ldg(bp + row0 + j);
        #pragma unroll
        for (int q = 0; q < 3; q++)
            #pragma unroll
            for (int rr = 0; rr < 4; rr++)
                Wreg[j * 12 + q * 4 + rr] = __ldg(Wp + (row0 + j) * 24 + q * 8 + h * 4 + rr);
    }

    const int quad   = (blockIdx.x * NTHREADS + t) >> 2;
    const int nquads = (NBLOCKS * NTHREADS) >> 2;
    const int niter  = (n + nquads - 1) / nquads;   // uniform across lanes

    for (int k = 0; k < niter; k++) {
        const int  i   = quad + k * nquads;
        const bool act = (i < n);
        const int  ie  = act ? i : 0;

        float cx = __ldg(coords + 3 * ie + 0);
        float cy = __ldg(coords + 3 * ie + 1);
        float cz = __ldg(coords + 3 * ie + 2);
        cx = fminf(fmaxf(cx, -1.0f), 1.0f);
        cy = fminf(fmaxf(cy, -1.0f), 1.0f);
        cz = fminf(fmaxf(cz, -1.0f), 1.0f);

        const PS a = plane_setup(cx, cy, s, r);
        const PS b = plane_setup(cx, cz, s, r);
        const PS c = plane_setup(cy, cz, s, r);

        // 6 independent gathers; per point each plane is ONE 128B region.
        // lane s: slot s of col-x0 entry, slot s of col-x1 entry (base+4).
        const float4 a0 = __ldg(dxy + a.base + s);
        const float4 a1 = __ldg(dxy + a.base + 4 + s);
        const float4 b0 = __ldg(dxz + b.base + s);
        const float4 b1 = __ldg(dxz + b.base + 4 + s);
        const float4 c0 = __ldg(dyz + c.base + s);
        const float4 c1 = __ldg(dyz + c.base + 4 + s);

        // partial features (this lane's row & half): x-lerp with fused weights
        float pf[12];
        pf[0]  = a.w0 * a0.x + a.w1 * a1.x;
        pf[1]  = a.w0 * a0.y + a.w1 * a1.y;
        pf[2]  = a.w0 * a0.z + a.w1 * a1.z;
        pf[3]  = a.w0 * a0.w + a.w1 * a1.w;
        pf[4]  = b.w0 * b0.x + b.w1 * b1.x;
        pf[5]  = b.w0 * b0.y + b.w1 * b1.y;
        pf[6]  = b.w0 * b0.z + b.w1 * b1.z;
        pf[7]  = b.w0 * b0.w + b.w1 * b1.w;
        pf[8]  = c.w0 * c0.x + c.w1 * c1.x;
        pf[9]  = c.w0 * c0.y + c.w1 * c1.y;
        pf[10] = c.w0 * c0.z + c.w1 * c1.z;
        pf[11] = c.w0 * c0.w + c.w1 * c1.w;

        // fused row-reduce (xor bit1) + register matvec
        float o0 = 0.f, o1 = 0.f, o2 = 0.f, o3 = 0.f;
        #pragma unroll
        for (int q = 0; q < 12; q++) {
            const float g = pf[q] + __shfl_xor_sync(0xffffffffu, pf[q], 2);
            o0 += Wreg[q]      * g;
            o1 += Wreg[12 + q] * g;
            o2 += Wreg[24 + q] * g;
            o3 += Wreg[36 + q] * g;
        }

        // combine rank halves (xor bit0)
        o0 += __shfl_xor_sync(0xffffffffu, o0, 1);
        o1 += __shfl_xor_sync(0xffffffffu, o1, 1);
        o2 += __shfl_xor_sync(0xffffffffu, o2, 1);
        o3 += __shfl_xor_sync(0xffffffffu, o3, 1);

        if (act && h == 0) {
            float4 v;
            v.x = fminf(fmaxf(o0 + bias[0], -10.0f), 10.0f);
            v.y = fminf(fmaxf(o1 + bias[1], -10.0f), 10.0f);
            v.z = fminf(fmaxf(o2 + bias[2], -10.0f), 10.0f);
            v.w = fminf(fmaxf(o3 + bias[3], -10.0f), 10.0f);
            reinterpret_cast<float4*>(out)[(i << 1) + grp] = v;
        }
    }
}

extern "C" void kernel_launch(void* const* d_in, const int* in_sizes, int n_in,
                              void* d_out, int out_size)
{
    const float*  coords = (const float*)d_in[0];
    const float4* pxy    = (const float4*)d_in[1];
    const float4* pxz    = (const float4*)d_in[2];
    const float4* pyz    = (const float4*)d_in[3];
    const float*  Wp     = (const float*)d_in[4];
    const float*  bp     = (const float*)d_in[5];
    float*        out    = (float*)d_out;

    const int n = in_sizes[0] / 3;

    const int repack_threads = 3 * DUP_F4;
    repack_kernel<<<repack_threads / 256, 256>>>(pxy, pxz, pyz);
    geo_encoder_kernel<<<NBLOCKS, NTHREADS>>>(coords, Wp, bp, out, n);
}

// round 9
// speedup vs baseline: 1.0920x; 1.0920x over previous
#include <cuda_runtime.h>

#define NTHREADS 256
#define BLOCKS_PER_SM 3
#define NBLOCKS  (148 * BLOCKS_PER_SM)   // persistent grid for gather

// Duplicated row-pair layout: entry(y,x) = 4 float4 =
//   [tex(y,x).h0, tex(y,x).h1, tex(y+1,x).h0, tex(y+1,x).h1]   (y+1 clamped to 511)
// One bilinear sample = one contiguous 128B region (entries x0, x0+1).
#define DUP_F4 (512 * 512 * 4)           // float4 count per plane (2^20)
__device__ float4 g_dup[3][DUP_F4];      // 3 x 16.8MB = 50MB static scratch

// ---- cache-policy memory ops (createpolicy + L2::cache_hint: width-agnostic) ----
__device__ __forceinline__ unsigned long long mk_evict_last_policy() {
    unsigned long long pol;
    asm("createpolicy.fractional.L2::evict_last.b64 %0, 1.0;" : "=l"(pol));
    return pol;
}
__device__ __forceinline__ float4 ld_keep(const float4* p, unsigned long long pol) {
    float4 v;
    asm volatile("ld.global.nc.L2::cache_hint.v4.f32 {%0,%1,%2,%3}, [%4], %5;"
                 : "=f"(v.x), "=f"(v.y), "=f"(v.z), "=f"(v.w) : "l"(p), "l"(pol));
    return v;
}
__device__ __forceinline__ void st_keep(float4* p, float4 v, unsigned long long pol) {
    asm volatile("st.global.L2::cache_hint.v4.f32 [%0], {%1,%2,%3,%4}, %5;"
                 :: "l"(p), "f"(v.x), "f"(v.y), "f"(v.z), "f"(v.w), "l"(pol));
}
__device__ __forceinline__ float ld_stream(const float* p) {   // streaming read
    float v;
    asm volatile("ld.global.cs.f32 %0, [%1];" : "=f"(v) : "l"(p));
    return v;
}
__device__ __forceinline__ void st_stream(float4* p, float4 v) {  // streaming write
    asm volatile("st.global.cs.v4.f32 [%0], {%1,%2,%3,%4};"
                 :: "l"(p), "f"(v.x), "f"(v.y), "f"(v.z), "f"(v.w));
}

__global__ void __launch_bounds__(256)
repack_kernel(const float4* __restrict__ p0,
              const float4* __restrict__ p1,
              const float4* __restrict__ p2)
{
    const int idx = blockIdx.x * 256 + threadIdx.x;   // one thread per output float4
    if (idx >= 3 * DUP_F4) return;
    const unsigned long long pol = mk_evict_last_policy();
    const int q    = idx >> 20;            // plane
    const int r    = idx & (DUP_F4 - 1);
    const int ent  = r >> 2;               // entry = y*512 + x
    const int slot = r & 3;
    const int y    = ent >> 9;
    const int x    = ent & 511;
    const int yy   = (slot < 2) ? y : min(y + 1, 511);
    const int h    = slot & 1;
    const float4* src = (q == 0) ? p0 : (q == 1) ? p1 : p2;
    st_keep(&g_dup[q][r], __ldg(src + ((((yy << 9) + x) << 1) + h)), pol);
}

struct PS { int base; float w0, w1; };   // w0/w1 = row-weight x (col0/col1 weight)

// Per-plane params for one lane (sub-lane s, row r = s>>1).
__device__ __forceinline__ PS plane_setup(float u, float v, int s, int r)
{
    // x = ((u+1)*512 - 1)*0.5 == u*256 + 255.5 (<=1 ulp; bilinear continuous)
    float x = fmaf(u, 256.0f, 255.5f);
    float y = fmaf(v, 256.0f, 255.5f);
    x = fminf(fmaxf(x, 0.0f), 511.0f);
    y = fminf(fmaxf(y, 0.0f), 511.0f);

    float xbf = fminf(floorf(x), 510.0f);
    float ybf = fminf(floorf(y), 510.0f);

    // a1 = weight of col xb+1 (== wx normally; ==1 exactly at border x=511)
    float a1 = x - xbf;
    float b1 = y - ybf;
    float rw = r ? b1 : (1.0f - b1);

    PS ps;
    ps.w0 = rw * (1.0f - a1);
    ps.w1 = rw * a1;
    ps.base = ((((int)ybf << 9) + (int)xbf) << 2);  // f4 idx of entry (yb, xb)
    return ps;
}

__global__ void __launch_bounds__(NTHREADS, BLOCKS_PER_SM)
geo_encoder_kernel(
    const float*  __restrict__ coords,   // [N,3]
    const float*  __restrict__ Wp,       // [8,24]
    const float*  __restrict__ bp,       // [8]
    float*        __restrict__ out,      // [N,8]
    int n)
{
    const float4* __restrict__ dxy = g_dup[0];
    const float4* __restrict__ dxz = g_dup[1];
    const float4* __restrict__ dyz = g_dup[2];

    const unsigned long long pol = mk_evict_last_policy();

    const int t   = threadIdx.x;
    const int s   = t & 3;       // sub-lane in quad
    const int h   = s & 1;       // rank half (float4 slot within texel)
    const int r   = s >> 1;      // row (top/bottom) this lane loads; also output group
    const int grp = r;

    // W slice in registers: Wreg[j*12 + q*4 + rr] = W[4*grp+j][q*8 + h*4 + rr]
    float Wreg[48];
    float bias[4];
    const int row0 = 4 * grp;
    #pragma unroll
    for (int j = 0; j < 4; j++) {
        bias[j] = __ldg(bp + row0 + j);
        #pragma unroll
        for (int q = 0; q < 3; q++)
            #pragma unroll
            for (int rr = 0; rr < 4; rr++)
                Wreg[j * 12 + q * 4 + rr] = __ldg(Wp + (row0 + j) * 24 + q * 8 + h * 4 + rr);
    }

    const int quad   = (blockIdx.x * NTHREADS + t) >> 2;
    const int nquads = (NBLOCKS * NTHREADS) >> 2;
    const int niter  = (n + nquads - 1) / nquads;   // uniform across lanes

    for (int k = 0; k < niter; k++) {
        const int  i   = quad + k * nquads;
        const bool act = (i < n);
        const int  ie  = act ? i : 0;

        float cx = ld_stream(coords + 3 * ie + 0);
        float cy = ld_stream(coords + 3 * ie + 1);
        float cz = ld_stream(coords + 3 * ie + 2);
        cx = fminf(fmaxf(cx, -1.0f), 1.0f);
        cy = fminf(fmaxf(cy, -1.0f), 1.0f);
        cz = fminf(fmaxf(cz, -1.0f), 1.0f);

        const PS a = plane_setup(cx, cy, s, r);
        const PS b = plane_setup(cx, cz, s, r);
        const PS c = plane_setup(cy, cz, s, r);

        // 6 independent gathers; per point each plane is ONE 128B region.
        // lane s: slot s of col-x0 entry, slot s of col-x1 entry (base+4).
        const float4 a0 = ld_keep(dxy + a.base + s, pol);
        const float4 a1 = ld_keep(dxy + a.base + 4 + s, pol);
        const float4 b0 = ld_keep(dxz + b.base + s, pol);
        const float4 b1 = ld_keep(dxz + b.base + 4 + s, pol);
        const float4 c0 = ld_keep(dyz + c.base + s, pol);
        const float4 c1 = ld_keep(dyz + c.base + 4 + s, pol);

        // partial features (this lane's row & half): x-lerp with fused weights
        float pf[12];
        pf[0]  = a.w0 * a0.x + a.w1 * a1.x;
        pf[1]  = a.w0 * a0.y + a.w1 * a1.y;
        pf[2]  = a.w0 * a0.z + a.w1 * a1.z;
        pf[3]  = a.w0 * a0.w + a.w1 * a1.w;
        pf[4]  = b.w0 * b0.x + b.w1 * b1.x;
        pf[5]  = b.w0 * b0.y + b.w1 * b1.y;
        pf[6]  = b.w0 * b0.z + b.w1 * b1.z;
        pf[7]  = b.w0 * b0.w + b.w1 * b1.w;
        pf[8]  = c.w0 * c0.x + c.w1 * c1.x;
        pf[9]  = c.w0 * c0.y + c.w1 * c1.y;
        pf[10] = c.w0 * c0.z + c.w1 * c1.z;
        pf[11] = c.w0 * c0.w + c.w1 * c1.w;

        // fused row-reduce (xor bit1) + register matvec
        float o0 = 0.f, o1 = 0.f, o2 = 0.f, o3 = 0.f;
        #pragma unroll
        for (int q = 0; q < 12; q++) {
            const float g = pf[q] + __shfl_xor_sync(0xffffffffu, pf[q], 2);
            o0 += Wreg[q]      * g;
            o1 += Wreg[12 + q] * g;
            o2 += Wreg[24 + q] * g;
            o3 += Wreg[36 + q] * g;
        }

        // combine rank halves (xor bit0)
        o0 += __shfl_xor_sync(0xffffffffu, o0, 1);
        o1 += __shfl_xor_sync(0xffffffffu, o1, 1);
        o2 += __shfl_xor_sync(0xffffffffu, o2, 1);
        o3 += __shfl_xor_sync(0xffffffffu, o3, 1);

        if (act && h == 0) {
            float4 v;
            v.x = fminf(fmaxf(o0 + bias[0], -10.0f), 10.0f);
            v.y = fminf(fmaxf(o1 + bias[1], -10.0f), 10.0f);
            v.z = fminf(fmaxf(o2 + bias[2], -10.0f), 10.0f);
            v.w = fminf(fmaxf(o3 + bias[3], -10.0f), 10.0f);
            st_stream(reinterpret_cast<float4*>(out) + ((i << 1) + grp), v);
        }
    }
}

extern "C" void kernel_launch(void* const* d_in, const int* in_sizes, int n_in,
                              void* d_out, int out_size)
{
    const float*  coords = (const float*)d_in[0];
    const float4* pxy    = (const float4*)d_in[1];
    const float4* pxz    = (const float4*)d_in[2];
    const float4* pyz    = (const float4*)d_in[3];
    const float*  Wp     = (const float*)d_in[4];
    const float*  bp     = (const float*)d_in[5];
    float*        out    = (float*)d_out;

    const int n = in_sizes[0] / 3;

    const int repack_threads = 3 * DUP_F4;
    repack_kernel<<<repack_threads / 256, 256>>>(pxy, pxz, pyz);
    geo_encoder_kernel<<<NBLOCKS, NTHREADS>>>(coords, Wp, bp, out, n);
}